// round 9
// baseline (speedup 1.0000x reference)
#include <cuda_runtime.h>
#include <cstdint>

#define BB 32
#define CC 256
#define HWL 3136                // 56*56
#define HID 32
#define NPLANE (BB*CC)          // 8192
#define PLANE_BYTES (HWL * 4)   // 12544
#define NP 16                   // planes per CTA
#define NCTA (NPLANE / NP)      // 512
#define CPB (CC / NP)           // 16 CTAs per batch
#define RING 4

#define SMEM_BUFS   (RING * PLANE_BYTES)                 // 50176
#define SMEM_TOTAL  (SMEM_BUFS + RING * 8 + (8 + CC + HID + 4 * NP) * 4)

__device__ float g_pooled[NPLANE];
__device__ unsigned g_bcnt[BB];

__device__ __forceinline__ uint32_t smem_u32(const void* p) {
    return (uint32_t)__cvta_generic_to_shared(p);
}
__device__ __forceinline__ void mbar_init(uint32_t mbar, uint32_t cnt) {
    asm volatile("mbarrier.init.shared.b64 [%0], %1;" :: "r"(mbar), "r"(cnt) : "memory");
}
__device__ __forceinline__ void mbar_expect_tx(uint32_t mbar, uint32_t bytes) {
    asm volatile("mbarrier.arrive.expect_tx.shared.b64 _, [%0], %1;"
                 :: "r"(mbar), "r"(bytes) : "memory");
}
__device__ __forceinline__ void mbar_wait(uint32_t mbar, uint32_t parity) {
    asm volatile(
        "{\n\t"
        ".reg .pred P;\n\t"
        "W_%=:\n\t"
        "mbarrier.try_wait.parity.shared.b64 P, [%0], %1;\n\t"
        "@!P bra W_%=;\n\t"
        "}"
        :: "r"(mbar), "r"(parity) : "memory");
}
__device__ __forceinline__ void tma_load_1d(uint32_t dst, const void* src,
                                            uint32_t bytes, uint32_t mbar) {
    asm volatile(
        "cp.async.bulk.shared::cluster.global.mbarrier::complete_tx::bytes "
        "[%0], [%1], %2, [%3];"
        :: "r"(dst), "l"(src), "r"(bytes), "r"(mbar) : "memory");
}
__device__ __forceinline__ void tma_store_1d(void* dst, uint32_t src, uint32_t bytes) {
    asm volatile("cp.async.bulk.global.shared::cta.bulk_group [%0], [%1], %2;"
                 :: "l"(dst), "r"(src), "r"(bytes) : "memory");
}

__global__ __launch_bounds__(256, 4) void fused_kernel(
        const float* __restrict__ x,
        const float* __restrict__ fc1_w,
        const float* __restrict__ fc1_b,
        const float* __restrict__ fc2_w,
        const float* __restrict__ fc2_b,
        float* __restrict__ out) {
    extern __shared__ char smraw[];
    float (*buf)[HWL] = reinterpret_cast<float(*)[HWL]>(smraw);
    unsigned long long* mb = reinterpret_cast<unsigned long long*>(smraw + SMEM_BUFS);
    float* ws  = reinterpret_cast<float*>(smraw + SMEM_BUFS + RING * 8);
    float* p_s = ws + 8;
    float* h_s = p_s + CC;
    float* sA0 = h_s + HID;
    float* sC0 = sA0 + NP;
    float* sA1 = sC0 + NP;
    float* sC1 = sA1 + NP;

    const int tid = threadIdx.x;
    const int lane = tid & 31;
    const int warp = tid >> 5;
    const int j = blockIdx.x;
    const int b = j / CPB;                     // batch
    const int cbase = (j % CPB) * NP;          // first channel
    const int base = j * NP;                   // first plane

    uint32_t mba[RING], bufa[RING];
#pragma unroll
    for (int r = 0; r < RING; r++) { mba[r] = smem_u32(&mb[r]); bufa[r] = smem_u32(buf[r]); }

    if (tid == 0) {
#pragma unroll
        for (int r = 0; r < RING; r++) mbar_init(mba[r], 1);
    }
    __syncthreads();

    uint32_t ph[RING] = {0, 0, 0, 0};

    // ---------------- Phase 1: pool 16 planes, prefetch depth 3 -------------
    if (tid == 0) {
#pragma unroll
        for (int s = 0; s < 3; s++) {
            mbar_expect_tx(mba[s], PLANE_BYTES);
            tma_load_1d(bufa[s], x + (size_t)(base + s) * HWL, PLANE_BYTES, mba[s]);
        }
    }
#pragma unroll
    for (int p = 0; p < NP; p++) {
        const int cur = p & 3;
        if (tid == 0 && p + 3 < NP) {
            const int nxt = (p + 3) & 3;       // slot of plane p-1, free since end of iter p-1
            mbar_expect_tx(mba[nxt], PLANE_BYTES);
            tma_load_1d(bufa[nxt], x + (size_t)(base + p + 3) * HWL, PLANE_BYTES, mba[nxt]);
        }
        mbar_wait(mba[cur], ph[cur]); ph[cur] ^= 1;

        const float4* t4 = reinterpret_cast<const float4*>(buf[cur]);
        float4 v0 = t4[tid];
        float4 v1 = t4[tid + 256];
        float4 v2 = t4[tid + 512];
        float s = (v0.x + v0.y) + (v0.z + v0.w)
                + (v1.x + v1.y) + (v1.z + v1.w)
                + (v2.x + v2.y) + (v2.z + v2.w);
        if (tid < 16) {
            float4 v3 = t4[768 + tid];
            s += (v3.x + v3.y) + (v3.z + v3.w);
        }
#pragma unroll
        for (int o = 16; o > 0; o >>= 1) s += __shfl_xor_sync(0xffffffffu, s, o);
        if (lane == 0) ws[warp] = s;
        __syncthreads();
        if (tid < 8) {
            s = ws[tid];
#pragma unroll
            for (int o = 4; o > 0; o >>= 1) s += __shfl_xor_sync(0xffu, s, o);
            if (tid == 0) g_pooled[base + p] = s * (1.0f / HWL);
        }
        __syncthreads();   // buf[cur] reads done before reuse
    }

    // Prefetch first apply plane BEFORE the barrier: hides spin + MLP latency.
    if (tid == 0) {
        mbar_expect_tx(mba[0], PLANE_BYTES);
        tma_load_1d(bufa[0], x + (size_t)base * HWL, PLANE_BYTES, mba[0]);
    }

    // ---------------- Per-batch sync ----------------------------------------
    if (tid == 0) {
        __threadfence();
        atomicAdd(&g_bcnt[b], 1u);
        volatile unsigned* cnt = (volatile unsigned*)&g_bcnt[b];
        while (*cnt < CPB) { __nanosleep(200); }
        __threadfence();
    }
    __syncthreads();

    // ---------------- Phase 2: tiny MLP + coefficients ----------------------
    p_s[tid] = __ldcg(&g_pooled[b * CC + tid]);
    __syncthreads();
    {
        const int jj = tid >> 3;
        const int part = tid & 7;
        const float* wrow = fc1_w + jj * CC + part * 32;
        const float* pp = p_s + part * 32;
        float acc = 0.f;
#pragma unroll
        for (int i2 = 0; i2 < 32; i2++) acc = fmaf(pp[i2], wrow[i2], acc);
#pragma unroll
        for (int o = 4; o > 0; o >>= 1) acc += __shfl_down_sync(0xffffffffu, acc, o, 8);
        if (part == 0) h_s[jj] = fmaxf(acc + fc1_b[jj], 0.f);
    }
    __syncthreads();

#pragma unroll
    for (int t = 0; t < 2; t++) {
        const int lp = warp * 2 + t;             // local plane 0..15
        const int c = cbase + lp;
        const float* wa0 = fc2_w + (size_t)(2 * c) * HID;
        const float* wb0 = wa0 + HID;
        const float* wa1 = fc2_w + (size_t)(2 * CC + 2 * c) * HID;
        const float* wb1 = wa1 + HID;
        float da0 = fc2_b[2 * c];
        float db0 = fc2_b[2 * c + 1];
        float da1 = fc2_b[2 * CC + 2 * c];
        float db1 = fc2_b[2 * CC + 2 * c + 1];
#pragma unroll
        for (int q = 0; q < HID; q++) {
            float hq = h_s[q];
            da0 = fmaf(wa0[q], hq, da0);
            db0 = fmaf(wb0[q], hq, db0);
            da1 = fmaf(wa1[q], hq, da1);
            db1 = fmaf(wb1[q], hq, db1);
        }
        if (lane == 0) {
            sA0[lp] = 1.0f + tanhf(0.5f * da0);          // LAMBDA_ALPHA = 1.0
            sC0[lp] = 1.0f + 0.5f * tanhf(0.5f * db0);   // LAMBDA_BETA  = 0.5
            sA1[lp] = tanhf(0.5f * da1);
            sC1[lp] = 0.5f * tanhf(0.5f * db1);
        }
    }
    __syncthreads();

    // ---------------- Phase 3: apply, depth-1 loads, stores 2-iter slack ----
#pragma unroll
    for (int p = 0; p < NP; p++) {
        const int cur = p & 3;
        if (tid == 0 && p + 1 < NP) {
            const int nxt = (p + 1) & 3;   // slot of apply plane p-3: its store
                                           // committed at end of iter p-3; allow
                                           // p-2, p-1 pending -> wait_group 2
            asm volatile("cp.async.bulk.wait_group 2;" ::: "memory");
            mbar_expect_tx(mba[nxt], PLANE_BYTES);
            tma_load_1d(bufa[nxt], x + (size_t)(base + p + 1) * HWL, PLANE_BYTES, mba[nxt]);
        }
        mbar_wait(mba[cur], ph[cur]); ph[cur] ^= 1;

        const float a0 = sA0[p], c0 = sC0[p], a1 = sA1[p], c1 = sC1[p];
        float4* t4 = reinterpret_cast<float4*>(buf[cur]);
        float4 v0 = t4[tid];
        float4 v1 = t4[tid + 256];
        float4 v2 = t4[tid + 512];
        float4 r0, r1, r2;
        r0.x = fmaxf(fmaf(v0.x, a0, c0), fmaf(v0.x, a1, c1));
        r0.y = fmaxf(fmaf(v0.y, a0, c0), fmaf(v0.y, a1, c1));
        r0.z = fmaxf(fmaf(v0.z, a0, c0), fmaf(v0.z, a1, c1));
        r0.w = fmaxf(fmaf(v0.w, a0, c0), fmaf(v0.w, a1, c1));
        r1.x = fmaxf(fmaf(v1.x, a0, c0), fmaf(v1.x, a1, c1));
        r1.y = fmaxf(fmaf(v1.y, a0, c0), fmaf(v1.y, a1, c1));
        r1.z = fmaxf(fmaf(v1.z, a0, c0), fmaf(v1.z, a1, c1));
        r1.w = fmaxf(fmaf(v1.w, a0, c0), fmaf(v1.w, a1, c1));
        r2.x = fmaxf(fmaf(v2.x, a0, c0), fmaf(v2.x, a1, c1));
        r2.y = fmaxf(fmaf(v2.y, a0, c0), fmaf(v2.y, a1, c1));
        r2.z = fmaxf(fmaf(v2.z, a0, c0), fmaf(v2.z, a1, c1));
        r2.w = fmaxf(fmaf(v2.w, a0, c0), fmaf(v2.w, a1, c1));
        t4[tid]       = r0;
        t4[tid + 256] = r1;
        t4[tid + 512] = r2;
        if (tid < 16) {
            float4 v3 = t4[768 + tid];
            float4 r3;
            r3.x = fmaxf(fmaf(v3.x, a0, c0), fmaf(v3.x, a1, c1));
            r3.y = fmaxf(fmaf(v3.y, a0, c0), fmaf(v3.y, a1, c1));
            r3.z = fmaxf(fmaf(v3.z, a0, c0), fmaf(v3.z, a1, c1));
            r3.w = fmaxf(fmaf(v3.w, a0, c0), fmaf(v3.w, a1, c1));
            t4[768 + tid] = r3;
        }
        __syncthreads();
        if (tid == 0) {
            asm volatile("fence.proxy.async.shared::cta;" ::: "memory");
            tma_store_1d(out + (size_t)(base + p) * HWL, bufa[cur], PLANE_BYTES);
            asm volatile("cp.async.bulk.commit_group;" ::: "memory");
        }
    }
    if (tid == 0) asm volatile("cp.async.bulk.wait_group 0;" ::: "memory");
}

extern "C" void kernel_launch(void* const* d_in, const int* in_sizes, int n_in,
                              void* d_out, int out_size) {
    const float* x      = (const float*)d_in[0];
    const float* fc1_w  = (const float*)d_in[1];
    const float* fc1_b  = (const float*)d_in[2];
    const float* fc2_w  = (const float*)d_in[3];
    const float* fc2_b  = (const float*)d_in[4];
    float* out = (float*)d_out;

    cudaFuncSetAttribute(fused_kernel,
                         cudaFuncAttributeMaxDynamicSharedMemorySize, SMEM_TOTAL);

    // reset per-batch counters every call (graph-capturable memset node)
    void* cnt_ptr = nullptr;
    cudaGetSymbolAddress(&cnt_ptr, g_bcnt);
    cudaMemsetAsync(cnt_ptr, 0, BB * sizeof(unsigned), 0);

    fused_kernel<<<NCTA, 256, SMEM_TOTAL>>>(x, fc1_w, fc1_b, fc2_w, fc2_b, out);
}

// round 10
// speedup vs baseline: 1.0771x; 1.0771x over previous
#include <cuda_runtime.h>
#include <cstdint>

#define BB 32
#define CC 256
#define HWL 3136                // 56*56
#define HID 32
#define NPLANE (BB*CC)          // 8192
#define PLANE_BYTES (HWL * 4)   // 12544

__device__ float g_pooled[NPLANE];
__device__ float g_a0[NPLANE];
__device__ float g_c0[NPLANE];
__device__ float g_a1[NPLANE];
__device__ float g_c1[NPLANE];

__device__ __forceinline__ uint32_t smem_u32(const void* p) {
    return (uint32_t)__cvta_generic_to_shared(p);
}

// ---------------------------------------------------------------------------
// Kernel 1: mean over H*W per plane. ONE WARP per plane. (proven ~19.9us)
// ---------------------------------------------------------------------------
__global__ __launch_bounds__(256) void pool_kernel(const float* __restrict__ x) {
    const int warp = (blockIdx.x << 3) | (threadIdx.x >> 5);
    const int lane = threadIdx.x & 31;
    const float4* xp = reinterpret_cast<const float4*>(x + (size_t)warp * HWL);

    float s = 0.f;
    int i = lane;
#pragma unroll 12
    for (int it = 0; it < 24; it++, i += 32) {
        float4 v = __ldg(&xp[i]);
        s += (v.x + v.y) + (v.z + v.w);
    }
    if (lane < 16) {
        float4 v = __ldg(&xp[768 + lane]);
        s += (v.x + v.y) + (v.z + v.w);
    }
#pragma unroll
    for (int o = 16; o > 0; o >>= 1) s += __shfl_xor_sync(0xffffffffu, s, o);
    if (lane == 0) g_pooled[warp] = s * (1.0f / HWL);
}

// ---------------------------------------------------------------------------
// Kernel 2: tiny MLP -> per-plane coefficient tables (128 KB, L2-resident).
// ---------------------------------------------------------------------------
__global__ __launch_bounds__(256) void coef_kernel(const float* __restrict__ fc1_w,
                                                   const float* __restrict__ fc1_b,
                                                   const float* __restrict__ fc2_w,
                                                   const float* __restrict__ fc2_b) {
    const int b = blockIdx.x;
    __shared__ float p_s[CC];
    __shared__ float h_s[HID];

    p_s[threadIdx.x] = g_pooled[b * CC + threadIdx.x];
    __syncthreads();

    {
        const int j = threadIdx.x >> 3;
        const int part = threadIdx.x & 7;
        const float* wrow = fc1_w + j * CC + part * 32;
        const float* pp = p_s + part * 32;
        float acc = 0.f;
#pragma unroll
        for (int i2 = 0; i2 < 32; i2++) acc = fmaf(pp[i2], wrow[i2], acc);
#pragma unroll
        for (int o = 4; o > 0; o >>= 1) acc += __shfl_down_sync(0xffffffffu, acc, o, 8);
        if (part == 0) h_s[j] = fmaxf(acc + fc1_b[j], 0.f);
    }
    __syncthreads();

    const int c = threadIdx.x;
    const float* wa0 = fc2_w + (size_t)(2 * c) * HID;
    const float* wb0 = wa0 + HID;
    const float* wa1 = fc2_w + (size_t)(2 * CC + 2 * c) * HID;
    const float* wb1 = wa1 + HID;
    float da0 = fc2_b[2 * c];
    float db0 = fc2_b[2 * c + 1];
    float da1 = fc2_b[2 * CC + 2 * c];
    float db1 = fc2_b[2 * CC + 2 * c + 1];
#pragma unroll
    for (int j = 0; j < HID; j++) {
        float hj = h_s[j];
        da0 = fmaf(wa0[j], hj, da0);
        db0 = fmaf(wb0[j], hj, db0);
        da1 = fmaf(wa1[j], hj, da1);
        db1 = fmaf(wb1[j], hj, db1);
    }
    const int plane = b * CC + c;
    g_a0[plane] = 1.0f + tanhf(0.5f * da0);          // LAMBDA_ALPHA = 1.0
    g_c0[plane] = 1.0f + 0.5f * tanhf(0.5f * db0);   // LAMBDA_BETA  = 0.5
    g_a1[plane] = tanhf(0.5f * da1);
    g_c1[plane] = 0.5f * tanhf(0.5f * db1);
}

// ---------------------------------------------------------------------------
// Kernel 3: hybrid apply. One CTA per plane (grid 8192, 8 CTAs/SM).
// Reads: plain LDG (x mostly L2-resident after pool). Compute in registers.
// Writes: STS -> one TMA bulk store (keeps stores off the L1tex LDG/STG path).
// No mbarrier anywhere; latency hidden by 8-way CTA overlap per SM.
// ---------------------------------------------------------------------------
__global__ __launch_bounds__(256, 8) void apply_hybrid_kernel(
        const float* __restrict__ x,
        float* __restrict__ out) {
    __shared__ alignas(16) float tile[HWL];

    const int plane = blockIdx.x;
    const int tid = threadIdx.x;

    const float a0 = g_a0[plane];
    const float c0 = g_c0[plane];
    const float a1 = g_a1[plane];
    const float c1 = g_c1[plane];

    const float4* xp = reinterpret_cast<const float4*>(x + (size_t)plane * HWL);
    float4* t4 = reinterpret_cast<float4*>(tile);

    // 784 float4 over 256 threads: 3 each + 16-thread tail. Loads batched
    // up front for MLP=3+.
    float4 v0 = xp[tid];
    float4 v1 = xp[tid + 256];
    float4 v2 = xp[tid + 512];
    float4 r0, r1, r2;
    r0.x = fmaxf(fmaf(v0.x, a0, c0), fmaf(v0.x, a1, c1));
    r0.y = fmaxf(fmaf(v0.y, a0, c0), fmaf(v0.y, a1, c1));
    r0.z = fmaxf(fmaf(v0.z, a0, c0), fmaf(v0.z, a1, c1));
    r0.w = fmaxf(fmaf(v0.w, a0, c0), fmaf(v0.w, a1, c1));
    r1.x = fmaxf(fmaf(v1.x, a0, c0), fmaf(v1.x, a1, c1));
    r1.y = fmaxf(fmaf(v1.y, a0, c0), fmaf(v1.y, a1, c1));
    r1.z = fmaxf(fmaf(v1.z, a0, c0), fmaf(v1.z, a1, c1));
    r1.w = fmaxf(fmaf(v1.w, a0, c0), fmaf(v1.w, a1, c1));
    r2.x = fmaxf(fmaf(v2.x, a0, c0), fmaf(v2.x, a1, c1));
    r2.y = fmaxf(fmaf(v2.y, a0, c0), fmaf(v2.y, a1, c1));
    r2.z = fmaxf(fmaf(v2.z, a0, c0), fmaf(v2.z, a1, c1));
    r2.w = fmaxf(fmaf(v2.w, a0, c0), fmaf(v2.w, a1, c1));
    t4[tid]       = r0;
    t4[tid + 256] = r1;
    t4[tid + 512] = r2;
    if (tid < 16) {
        float4 v3 = xp[768 + tid];
        float4 r3;
        r3.x = fmaxf(fmaf(v3.x, a0, c0), fmaf(v3.x, a1, c1));
        r3.y = fmaxf(fmaf(v3.y, a0, c0), fmaf(v3.y, a1, c1));
        r3.z = fmaxf(fmaf(v3.z, a0, c0), fmaf(v3.z, a1, c1));
        r3.w = fmaxf(fmaf(v3.w, a0, c0), fmaf(v3.w, a1, c1));
        t4[768 + tid] = r3;
    }
    __syncthreads();

    if (tid == 0) {
        asm volatile("fence.proxy.async.shared::cta;" ::: "memory");
        asm volatile("cp.async.bulk.global.shared::cta.bulk_group [%0], [%1], %2;"
                     :: "l"(out + (size_t)plane * HWL), "r"(smem_u32(tile)),
                        "r"((uint32_t)PLANE_BYTES) : "memory");
        asm volatile("cp.async.bulk.commit_group;" ::: "memory");
        asm volatile("cp.async.bulk.wait_group 0;" ::: "memory");
    }
}

extern "C" void kernel_launch(void* const* d_in, const int* in_sizes, int n_in,
                              void* d_out, int out_size) {
    const float* x      = (const float*)d_in[0];
    const float* fc1_w  = (const float*)d_in[1];
    const float* fc1_b  = (const float*)d_in[2];
    const float* fc2_w  = (const float*)d_in[3];
    const float* fc2_b  = (const float*)d_in[4];
    float* out = (float*)d_out;

    pool_kernel<<<NPLANE / 8, 256>>>(x);
    coef_kernel<<<BB, 256>>>(fc1_w, fc1_b, fc2_w, fc2_b);
    apply_hybrid_kernel<<<NPLANE, 256>>>(x, out);
}

// round 11
// speedup vs baseline: 1.1052x; 1.0261x over previous
#include <cuda_runtime.h>
#include <cstdint>

#define BB 32
#define CC 256
#define HWL 3136                // 56*56
#define HID 32
#define NPLANE (BB*CC)          // 8192
#define PLANE_BYTES (HWL * 4)   // 12544

__device__ float g_pooled[NPLANE];
__device__ float g_a0[NPLANE];
__device__ float g_c0[NPLANE];
__device__ float g_a1[NPLANE];
__device__ float g_c1[NPLANE];

__device__ __forceinline__ uint32_t smem_u32(const void* p) {
    return (uint32_t)__cvta_generic_to_shared(p);
}

// ---------------------------------------------------------------------------
// Kernel 1: mean over H*W per plane. ONE WARP per plane. (proven ~19.6us)
// ---------------------------------------------------------------------------
__global__ __launch_bounds__(256) void pool_kernel(const float* __restrict__ x) {
    const int warp = (blockIdx.x << 3) | (threadIdx.x >> 5);
    const int lane = threadIdx.x & 31;
    const float4* xp = reinterpret_cast<const float4*>(x + (size_t)warp * HWL);

    float s = 0.f;
    int i = lane;
#pragma unroll 12
    for (int it = 0; it < 24; it++, i += 32) {
        float4 v = __ldg(&xp[i]);
        s += (v.x + v.y) + (v.z + v.w);
    }
    if (lane < 16) {
        float4 v = __ldg(&xp[768 + lane]);
        s += (v.x + v.y) + (v.z + v.w);
    }
#pragma unroll
    for (int o = 16; o > 0; o >>= 1) s += __shfl_xor_sync(0xffffffffu, s, o);
    if (lane == 0) g_pooled[warp] = s * (1.0f / HWL);
}

// ---------------------------------------------------------------------------
// Kernel 2: tiny MLP -> per-plane coefficient tables (128 KB, L2-resident).
// ---------------------------------------------------------------------------
__global__ __launch_bounds__(256) void coef_kernel(const float* __restrict__ fc1_w,
                                                   const float* __restrict__ fc1_b,
                                                   const float* __restrict__ fc2_w,
                                                   const float* __restrict__ fc2_b) {
    const int b = blockIdx.x;
    __shared__ float p_s[CC];
    __shared__ float h_s[HID];

    p_s[threadIdx.x] = g_pooled[b * CC + threadIdx.x];
    __syncthreads();

    {
        const int j = threadIdx.x >> 3;
        const int part = threadIdx.x & 7;
        const float* wrow = fc1_w + j * CC + part * 32;
        const float* pp = p_s + part * 32;
        float acc = 0.f;
#pragma unroll
        for (int i2 = 0; i2 < 32; i2++) acc = fmaf(pp[i2], wrow[i2], acc);
#pragma unroll
        for (int o = 4; o > 0; o >>= 1) acc += __shfl_down_sync(0xffffffffu, acc, o, 8);
        if (part == 0) h_s[j] = fmaxf(acc + fc1_b[j], 0.f);
    }
    __syncthreads();

    const int c = threadIdx.x;
    const float* wa0 = fc2_w + (size_t)(2 * c) * HID;
    const float* wb0 = wa0 + HID;
    const float* wa1 = fc2_w + (size_t)(2 * CC + 2 * c) * HID;
    const float* wb1 = wa1 + HID;
    float da0 = fc2_b[2 * c];
    float db0 = fc2_b[2 * c + 1];
    float da1 = fc2_b[2 * CC + 2 * c];
    float db1 = fc2_b[2 * CC + 2 * c + 1];
#pragma unroll
    for (int j = 0; j < HID; j++) {
        float hj = h_s[j];
        da0 = fmaf(wa0[j], hj, da0);
        db0 = fmaf(wb0[j], hj, db0);
        da1 = fmaf(wa1[j], hj, da1);
        db1 = fmaf(wb1[j], hj, db1);
    }
    const int plane = b * CC + c;
    g_a0[plane] = 1.0f + tanhf(0.5f * da0);          // LAMBDA_ALPHA = 1.0
    g_c0[plane] = 1.0f + 0.5f * tanhf(0.5f * db0);   // LAMBDA_BETA  = 0.5
    g_a1[plane] = tanhf(0.5f * da1);
    g_c1[plane] = 0.5f * tanhf(0.5f * db1);
}

// ---------------------------------------------------------------------------
// Kernel 3: hybrid apply, REVERSE plane order + evict-first bulk store.
// Reverse order: pool ended with the tail of x freshest in L2; start there.
// Evict-first store policy: out lines don't displace x in L2 (R3-proven
// effect, now on the bulk path with no L1tex per-instruction cost).
// ---------------------------------------------------------------------------
__global__ __launch_bounds__(256, 8) void apply_hybrid_kernel(
        const float* __restrict__ x,
        float* __restrict__ out) {
    __shared__ alignas(16) float tile[HWL];

    const int plane = (NPLANE - 1) - blockIdx.x;   // reverse traversal
    const int tid = threadIdx.x;

    const float a0 = g_a0[plane];
    const float c0 = g_c0[plane];
    const float a1 = g_a1[plane];
    const float c1 = g_c1[plane];

    const float4* xp = reinterpret_cast<const float4*>(x + (size_t)plane * HWL);
    float4* t4 = reinterpret_cast<float4*>(tile);

    float4 v0 = xp[tid];
    float4 v1 = xp[tid + 256];
    float4 v2 = xp[tid + 512];
    float4 r0, r1, r2;
    r0.x = fmaxf(fmaf(v0.x, a0, c0), fmaf(v0.x, a1, c1));
    r0.y = fmaxf(fmaf(v0.y, a0, c0), fmaf(v0.y, a1, c1));
    r0.z = fmaxf(fmaf(v0.z, a0, c0), fmaf(v0.z, a1, c1));
    r0.w = fmaxf(fmaf(v0.w, a0, c0), fmaf(v0.w, a1, c1));
    r1.x = fmaxf(fmaf(v1.x, a0, c0), fmaf(v1.x, a1, c1));
    r1.y = fmaxf(fmaf(v1.y, a0, c0), fmaf(v1.y, a1, c1));
    r1.z = fmaxf(fmaf(v1.z, a0, c0), fmaf(v1.z, a1, c1));
    r1.w = fmaxf(fmaf(v1.w, a0, c0), fmaf(v1.w, a1, c1));
    r2.x = fmaxf(fmaf(v2.x, a0, c0), fmaf(v2.x, a1, c1));
    r2.y = fmaxf(fmaf(v2.y, a0, c0), fmaf(v2.y, a1, c1));
    r2.z = fmaxf(fmaf(v2.z, a0, c0), fmaf(v2.z, a1, c1));
    r2.w = fmaxf(fmaf(v2.w, a0, c0), fmaf(v2.w, a1, c1));
    t4[tid]       = r0;
    t4[tid + 256] = r1;
    t4[tid + 512] = r2;
    if (tid < 16) {
        float4 v3 = xp[768 + tid];
        float4 r3;
        r3.x = fmaxf(fmaf(v3.x, a0, c0), fmaf(v3.x, a1, c1));
        r3.y = fmaxf(fmaf(v3.y, a0, c0), fmaf(v3.y, a1, c1));
        r3.z = fmaxf(fmaf(v3.z, a0, c0), fmaf(v3.z, a1, c1));
        r3.w = fmaxf(fmaf(v3.w, a0, c0), fmaf(v3.w, a1, c1));
        t4[768 + tid] = r3;
    }
    __syncthreads();

    if (tid == 0) {
        asm volatile("fence.proxy.async.shared::cta;" ::: "memory");
        asm volatile(
            "{\n\t"
            ".reg .b64 pol;\n\t"
            "createpolicy.fractional.L2::evict_first.b64 pol, 1.0;\n\t"
            "cp.async.bulk.global.shared::cta.bulk_group.L2::cache_hint "
            "[%0], [%1], %2, pol;\n\t"
            "}"
            :: "l"(out + (size_t)plane * HWL), "r"(smem_u32(tile)),
               "r"((uint32_t)PLANE_BYTES) : "memory");
        asm volatile("cp.async.bulk.commit_group;" ::: "memory");
        asm volatile("cp.async.bulk.wait_group 0;" ::: "memory");
    }
}

extern "C" void kernel_launch(void* const* d_in, const int* in_sizes, int n_in,
                              void* d_out, int out_size) {
    const float* x      = (const float*)d_in[0];
    const float* fc1_w  = (const float*)d_in[1];
    const float* fc1_b  = (const float*)d_in[2];
    const float* fc2_w  = (const float*)d_in[3];
    const float* fc2_b  = (const float*)d_in[4];
    float* out = (float*)d_out;

    pool_kernel<<<NPLANE / 8, 256>>>(x);
    coef_kernel<<<BB, 256>>>(fc1_w, fc1_b, fc2_w, fc2_b);
    apply_hybrid_kernel<<<NPLANE, 256>>>(x, out);
}